// round 3
// baseline (speedup 1.0000x reference)
#include <cuda_runtime.h>
#include <cstdint>

#define NP   200000
#define NU   50000
#define NNZE 2000000
#define DIM  64
#define NTOT (NP*DIM)      /* 12,800,000 */
#define MSGN (NU*DIM)      /*  3,200,000 */

__device__ __align__(16) float g_x[NTOT];
__device__ __align__(16) float g_acc[NTOT];
__device__ __align__(16) float g_prop[NTOT];
__device__ __align__(16) float g_msg[MSGN];

// ---------------- threefry2x32 (exact JAX semantics) ----------------
__host__ __device__ __forceinline__ uint32_t rotl32(uint32_t x, int d) {
    return (x << d) | (x >> (32 - d));
}

__host__ __device__ __forceinline__ void tf2x32(uint32_t k0, uint32_t k1,
                                                uint32_t x0, uint32_t x1,
                                                uint32_t &o0, uint32_t &o1) {
    uint32_t ks2 = k0 ^ k1 ^ 0x1BD11BDAu;
    x0 += k0; x1 += k1;
#define TFR(r) { x0 += x1; x1 = rotl32(x1, (r)); x1 ^= x0; }
    TFR(13) TFR(15) TFR(26) TFR(6)
    x0 += k1;  x1 += ks2 + 1u;
    TFR(17) TFR(29) TFR(16) TFR(24)
    x0 += ks2; x1 += k0 + 2u;
    TFR(13) TFR(15) TFR(26) TFR(6)
    x0 += k0;  x1 += k1 + 3u;
    TFR(17) TFR(29) TFR(16) TFR(24)
    x0 += k1;  x1 += ks2 + 4u;
    TFR(13) TFR(15) TFR(26) TFR(6)
    x0 += ks2; x1 += k0 + 5u;
#undef TFR
    o0 = x0; o1 = x1;
}

// partitionable threefry draw for element e (counter (0, e)), 32-bit: out0 ^ out1
__device__ __forceinline__ uint32_t tf_bits(uint32_t k0, uint32_t k1, uint32_t e) {
    uint32_t o0, o1;
    tf2x32(k0, k1, 0u, e, o0, o1);
    return o0 ^ o1;
}

// ---------------- kernels ----------------
__global__ void init_kernel(const float4* __restrict__ pois) {
    int i = blockIdx.x * blockDim.x + threadIdx.x;
    if (i < NTOT/4) {
        float4 v = pois[i];
        reinterpret_cast<float4*>(g_x)[i]   = v;
        reinterpret_cast<float4*>(g_acc)[i] = v;
    }
}

__global__ void zero_kernel() {
    int i = blockIdx.x * blockDim.x + threadIdx.x;
    float4 z = make_float4(0.f, 0.f, 0.f, 0.f);
    if (i < MSGN/4) reinterpret_cast<float4*>(g_msg)[i]  = z;
    if (i < NTOT/4) reinterpret_cast<float4*>(g_prop)[i] = z;
}

// half-warp (16 lanes) per nnz; each lane owns one float4 of the 64-float row
__global__ void spmm_kernel(const int*   __restrict__ rows,
                            const int*   __restrict__ cols,
                            const float* __restrict__ vals,
                            const float* __restrict__ xin,
                            float*       __restrict__ yout) {
    int t = blockIdx.x * blockDim.x + threadIdx.x;
    int e = t >> 4;
    if (e >= NNZE) return;
    int lane = t & 15;
    int r = __ldg(rows + e);
    int c = __ldg(cols + e);
    float v = __ldg(vals + e);
    float4 xv = *reinterpret_cast<const float4*>(xin + (size_t)c * DIM + lane * 4);
    float* addr = yout + (size_t)r * DIM + lane * 4;
    asm volatile("red.global.add.v4.f32 [%0], {%1,%2,%3,%4};"
                 :: "l"(addr), "f"(v * xv.x), "f"(v * xv.y), "f"(v * xv.z), "f"(v * xv.w)
                 : "memory");
}

__device__ __forceinline__ float dropv(uint32_t bits, float s) {
    // keep iff uniform < 0.5  <=>  MSB(bits) == 0 ; kept values scaled by 1/keep = 2
    return (bits & 0x80000000u) ? 0.f : 2.f * s;
}

// residual + dropout + acc; thread i owns 8 consecutive floats [8i .. 8i+7]
__global__ void update_kernel(uint32_t k0, uint32_t k1, int last,
                              float4* __restrict__ out) {
    int i = blockIdx.x * blockDim.x + threadIdx.x;
    if (i >= NTOT/8) return;
    uint32_t e = (uint32_t)i * 8u;

    uint32_t m[8];
#pragma unroll
    for (int j = 0; j < 8; ++j) m[j] = tf_bits(k0, k1, e + (uint32_t)j);

    int i0 = 2 * i, i1 = 2 * i + 1;
    float4 p0 = reinterpret_cast<float4*>(g_prop)[i0];
    float4 x0 = reinterpret_cast<float4*>(g_x)[i0];
    float4 a0 = reinterpret_cast<float4*>(g_acc)[i0];
    float4 p1 = reinterpret_cast<float4*>(g_prop)[i1];
    float4 x1 = reinterpret_cast<float4*>(g_x)[i1];
    float4 a1 = reinterpret_cast<float4*>(g_acc)[i1];

    float4 n0, n1;
    n0.x = dropv(m[0], p0.x + x0.x);
    n0.y = dropv(m[1], p0.y + x0.y);
    n0.z = dropv(m[2], p0.z + x0.z);
    n0.w = dropv(m[3], p0.w + x0.w);
    n1.x = dropv(m[4], p1.x + x1.x);
    n1.y = dropv(m[5], p1.y + x1.y);
    n1.z = dropv(m[6], p1.z + x1.z);
    n1.w = dropv(m[7], p1.w + x1.w);

    a0.x += n0.x; a0.y += n0.y; a0.z += n0.z; a0.w += n0.w;
    a1.x += n1.x; a1.y += n1.y; a1.z += n1.z; a1.w += n1.w;

    reinterpret_cast<float4*>(g_x)[i0]   = n0;
    reinterpret_cast<float4*>(g_x)[i1]   = n1;
    reinterpret_cast<float4*>(g_acc)[i0] = a0;
    reinterpret_cast<float4*>(g_acc)[i1] = a1;

    if (last) {
        out[i0] = make_float4(a0.x * 0.25f, a0.y * 0.25f, a0.z * 0.25f, a0.w * 0.25f);
        out[i1] = make_float4(a1.x * 0.25f, a1.y * 0.25f, a1.z * 0.25f, a1.w * 0.25f);
    }
}

// ---------------- launch ----------------
// Inputs in dict/insertion order:
//   d_in[0]=pois_embs, d_in[1]=up_rows, d_in[2]=up_cols, d_in[3]=up_vals,
//   d_in[4]=pu_rows,   d_in[5]=pu_cols, d_in[6]=pu_vals
extern "C" void kernel_launch(void* const* d_in, const int* in_sizes, int n_in,
                              void* d_out, int out_size) {
    const float* pois    = (const float*)d_in[0];
    const int*   up_rows = (const int*)  d_in[1];
    const int*   up_cols = (const int*)  d_in[2];
    const float* up_vals = (const float*)d_in[3];
    const int*   pu_rows = (const int*)  d_in[4];
    const int*   pu_cols = (const int*)  d_in[5];
    const float* pu_vals = (const float*)d_in[6];
    float* out = (float*)d_out;

    float *px, *pmsg, *pprop;
    cudaGetSymbolAddress((void**)&px,    g_x);
    cudaGetSymbolAddress((void**)&pmsg,  g_msg);
    cudaGetSymbolAddress((void**)&pprop, g_prop);

    // per-layer dropout keys: fold_in(key(42), l) = threefry((0,42),(0,l))
    uint32_t lk0[3], lk1[3];
    for (int l = 0; l < 3; ++l)
        tf2x32(0u, 42u, 0u, (uint32_t)l, lk0[l], lk1[l]);

    const int B = 256;
    init_kernel<<<(NTOT/4 + B - 1) / B, B>>>((const float4*)pois);
    for (int l = 0; l < 3; ++l) {
        zero_kernel<<<(NTOT/4 + B - 1) / B, B>>>();
        spmm_kernel<<<(NNZE * 16 + B - 1) / B, B>>>(up_rows, up_cols, up_vals, px,   pmsg);
        spmm_kernel<<<(NNZE * 16 + B - 1) / B, B>>>(pu_rows, pu_cols, pu_vals, pmsg, pprop);
        update_kernel<<<(NTOT/8 + B - 1) / B, B>>>(lk0[l], lk1[l], l == 2, (float4*)out);
    }
}

// round 4
// speedup vs baseline: 1.0738x; 1.0738x over previous
#include <cuda_runtime.h>
#include <cstdint>

#define NP   200000
#define NU   50000
#define NNZE 2000000
#define DIM  64
#define NTOT (NP*DIM)      /* 12,800,000 */
#define MSGN (NU*DIM)      /*  3,200,000 */

__device__ __align__(16) float g_x[NTOT];
__device__ __align__(16) float g_acc[NTOT];
__device__ __align__(16) float g_prop[NTOT];
__device__ __align__(16) float g_msg[MSGN];

// CSR scratch
__device__ int  g_up_ptr[NU + 1];
__device__ int  g_up_off[NU];
__device__ int2 g_up_cv[NNZE];     // packed (col, val-bits), row-sorted
__device__ int  g_pu_ptr[NP + 1];
__device__ int  g_pu_off[NP];
__device__ int2 g_pu_cv[NNZE];

// ---------------- threefry2x32 (exact JAX semantics) ----------------
__host__ __device__ __forceinline__ uint32_t rotl32(uint32_t x, int d) {
    return (x << d) | (x >> (32 - d));
}

__host__ __device__ __forceinline__ void tf2x32(uint32_t k0, uint32_t k1,
                                                uint32_t x0, uint32_t x1,
                                                uint32_t &o0, uint32_t &o1) {
    uint32_t ks2 = k0 ^ k1 ^ 0x1BD11BDAu;
    x0 += k0; x1 += k1;
#define TFR(r) { x0 += x1; x1 = rotl32(x1, (r)); x1 ^= x0; }
    TFR(13) TFR(15) TFR(26) TFR(6)
    x0 += k1;  x1 += ks2 + 1u;
    TFR(17) TFR(29) TFR(16) TFR(24)
    x0 += ks2; x1 += k0 + 2u;
    TFR(13) TFR(15) TFR(26) TFR(6)
    x0 += k0;  x1 += k1 + 3u;
    TFR(17) TFR(29) TFR(16) TFR(24)
    x0 += k1;  x1 += ks2 + 4u;
    TFR(13) TFR(15) TFR(26) TFR(6)
    x0 += ks2; x1 += k0 + 5u;
#undef TFR
    o0 = x0; o1 = x1;
}

// partitionable threefry draw for element e (counter (0, e)), 32-bit: out0 ^ out1
__device__ __forceinline__ uint32_t tf_bits(uint32_t k0, uint32_t k1, uint32_t e) {
    uint32_t o0, o1;
    tf2x32(k0, k1, 0u, e, o0, o1);
    return o0 ^ o1;
}

// ---------------- CSR build ----------------
__global__ void zero_cnt_kernel() {
    int i = blockIdx.x * blockDim.x + threadIdx.x;
    if (i <= NU) g_up_ptr[i] = 0;
    if (i <= NP) g_pu_ptr[i] = 0;
}

__global__ void hist_kernel(const int* __restrict__ up_rows,
                            const int* __restrict__ pu_rows) {
    int e = blockIdx.x * blockDim.x + threadIdx.x;
    if (e >= NNZE) return;
    atomicAdd(&g_up_ptr[__ldg(up_rows + e)], 1);
    atomicAdd(&g_pu_ptr[__ldg(pu_rows + e)], 1);
}

// single-block chunked exclusive scan, in place: cnt -> ptr (and off copy)
__global__ void scan_kernel(int* __restrict__ ptr, int* __restrict__ off, int n) {
    __shared__ int sm[1024];
    int t = threadIdx.x;
    int chunk = (n + 1023) / 1024;
    int lo = t * chunk, hi = min(lo + chunk, n);
    int s = 0;
    for (int i = lo; i < hi; ++i) s += ptr[i];
    sm[t] = s;
    __syncthreads();
    // inclusive Hillis-Steele scan of 1024 partials
    for (int d = 1; d < 1024; d <<= 1) {
        int v = (t >= d) ? sm[t - d] : 0;
        __syncthreads();
        sm[t] += v;
        __syncthreads();
    }
    int run = (t == 0) ? 0 : sm[t - 1];
    for (int i = lo; i < hi; ++i) {
        int v = ptr[i];          // read before overwrite (in place OK per thread)
        ptr[i] = run;
        off[i] = run;
        run += v;
    }
    if (t == 1023) ptr[n] = sm[1023];
    else if (hi == n && lo < n) ptr[n] = run;   // in case last chunk < thread 1023
}

__global__ void scatter_kernel(const int* __restrict__ up_rows,
                               const int* __restrict__ up_cols,
                               const float* __restrict__ up_vals,
                               const int* __restrict__ pu_rows,
                               const int* __restrict__ pu_cols,
                               const float* __restrict__ pu_vals) {
    int e = blockIdx.x * blockDim.x + threadIdx.x;
    if (e >= NNZE) return;
    {
        int r = __ldg(up_rows + e);
        int p = atomicAdd(&g_up_off[r], 1);
        g_up_cv[p] = make_int2(__ldg(up_cols + e), __float_as_int(__ldg(up_vals + e)));
    }
    {
        int r = __ldg(pu_rows + e);
        int p = atomicAdd(&g_pu_off[r], 1);
        g_pu_cv[p] = make_int2(__ldg(pu_cols + e), __float_as_int(__ldg(pu_vals + e)));
    }
}

// ---------------- CSR SpMM: one warp per row, float2 per lane ----------------
__global__ void spmm_csr_kernel(const int*  __restrict__ ptr,
                                const int2* __restrict__ cv,
                                const float* __restrict__ xin,
                                float*       __restrict__ yout,
                                int nrows) {
    int w = (blockIdx.x * blockDim.x + threadIdx.x) >> 5;
    if (w >= nrows) return;
    int lane = threadIdx.x & 31;
    int s = __ldg(ptr + w), epo = __ldg(ptr + w + 1);
    float2 acc = make_float2(0.f, 0.f);
    for (int j = s; j < epo; ++j) {
        int2 e = __ldg(cv + j);                  // same addr all lanes: L1 broadcast
        float v = __int_as_float(e.y);
        float2 xv = *reinterpret_cast<const float2*>(xin + (size_t)e.x * DIM + lane * 2);
        acc.x += v * xv.x;
        acc.y += v * xv.y;
    }
    *reinterpret_cast<float2*>(yout + (size_t)w * DIM + lane * 2) = acc;
}

// ---------------- residual + dropout + acc ----------------
__device__ __forceinline__ float dropv(uint32_t bits, float s) {
    return (bits & 0x80000000u) ? 0.f : 2.f * s;   // keep iff MSB==0, scale 1/keep=2
}

__global__ void update_kernel(uint32_t k0, uint32_t k1, int last,
                              const float4* __restrict__ x_in,
                              const float4* __restrict__ acc_in,
                              float4* __restrict__ out) {
    int i = blockIdx.x * blockDim.x + threadIdx.x;
    if (i >= NTOT / 8) return;
    uint32_t e = (uint32_t)i * 8u;

    uint32_t m[8];
#pragma unroll
    for (int j = 0; j < 8; ++j) m[j] = tf_bits(k0, k1, e + (uint32_t)j);

    int i0 = 2 * i, i1 = 2 * i + 1;
    float4 p0 = reinterpret_cast<float4*>(g_prop)[i0];
    float4 x0 = x_in[i0];
    float4 a0 = acc_in[i0];
    float4 p1 = reinterpret_cast<float4*>(g_prop)[i1];
    float4 x1 = x_in[i1];
    float4 a1 = acc_in[i1];

    float4 n0, n1;
    n0.x = dropv(m[0], p0.x + x0.x);
    n0.y = dropv(m[1], p0.y + x0.y);
    n0.z = dropv(m[2], p0.z + x0.z);
    n0.w = dropv(m[3], p0.w + x0.w);
    n1.x = dropv(m[4], p1.x + x1.x);
    n1.y = dropv(m[5], p1.y + x1.y);
    n1.z = dropv(m[6], p1.z + x1.z);
    n1.w = dropv(m[7], p1.w + x1.w);

    a0.x += n0.x; a0.y += n0.y; a0.z += n0.z; a0.w += n0.w;
    a1.x += n1.x; a1.y += n1.y; a1.z += n1.z; a1.w += n1.w;

    if (!last) {
        reinterpret_cast<float4*>(g_x)[i0]   = n0;
        reinterpret_cast<float4*>(g_x)[i1]   = n1;
        reinterpret_cast<float4*>(g_acc)[i0] = a0;
        reinterpret_cast<float4*>(g_acc)[i1] = a1;
    } else {
        out[i0] = make_float4(a0.x * 0.25f, a0.y * 0.25f, a0.z * 0.25f, a0.w * 0.25f);
        out[i1] = make_float4(a1.x * 0.25f, a1.y * 0.25f, a1.z * 0.25f, a1.w * 0.25f);
    }
}

// ---------------- launch ----------------
// Inputs in dict/insertion order:
//   d_in[0]=pois_embs, d_in[1]=up_rows, d_in[2]=up_cols, d_in[3]=up_vals,
//   d_in[4]=pu_rows,   d_in[5]=pu_cols, d_in[6]=pu_vals
extern "C" void kernel_launch(void* const* d_in, const int* in_sizes, int n_in,
                              void* d_out, int out_size) {
    const float* pois    = (const float*)d_in[0];
    const int*   up_rows = (const int*)  d_in[1];
    const int*   up_cols = (const int*)  d_in[2];
    const float* up_vals = (const float*)d_in[3];
    const int*   pu_rows = (const int*)  d_in[4];
    const int*   pu_cols = (const int*)  d_in[5];
    const float* pu_vals = (const float*)d_in[6];
    float* out = (float*)d_out;

    float *px, *pacc, *pmsg, *pprop;
    int *pup_ptr, *pup_off, *ppu_ptr, *ppu_off;
    int2 *pup_cv, *ppu_cv;
    cudaGetSymbolAddress((void**)&px,      g_x);
    cudaGetSymbolAddress((void**)&pacc,    g_acc);
    cudaGetSymbolAddress((void**)&pmsg,    g_msg);
    cudaGetSymbolAddress((void**)&pprop,   g_prop);
    cudaGetSymbolAddress((void**)&pup_ptr, g_up_ptr);
    cudaGetSymbolAddress((void**)&pup_off, g_up_off);
    cudaGetSymbolAddress((void**)&pup_cv,  g_up_cv);
    cudaGetSymbolAddress((void**)&ppu_ptr, g_pu_ptr);
    cudaGetSymbolAddress((void**)&ppu_off, g_pu_off);
    cudaGetSymbolAddress((void**)&ppu_cv,  g_pu_cv);

    // per-layer dropout keys: fold_in(key(42), l) = threefry((0,42),(0,l))
    uint32_t lk0[3], lk1[3];
    for (int l = 0; l < 3; ++l)
        tf2x32(0u, 42u, 0u, (uint32_t)l, lk0[l], lk1[l]);

    const int B = 256;

    // ---- CSR build (once per call, reused by all 3 layers) ----
    zero_cnt_kernel<<<(NP + 1 + B - 1) / B, B>>>();
    hist_kernel<<<(NNZE + B - 1) / B, B>>>(up_rows, pu_rows);
    scan_kernel<<<1, 1024>>>(pup_ptr, pup_off, NU);
    scan_kernel<<<1, 1024>>>(ppu_ptr, ppu_off, NP);
    scatter_kernel<<<(NNZE + B - 1) / B, B>>>(up_rows, up_cols, up_vals,
                                              pu_rows, pu_cols, pu_vals);

    // ---- 3 layers ----
    for (int l = 0; l < 3; ++l) {
        const float* xcur = (l == 0) ? pois : px;
        const float* acur = (l == 0) ? pois : pacc;
        spmm_csr_kernel<<<(NU * 32 + B - 1) / B, B>>>(pup_ptr, pup_cv, xcur, pmsg, NU);
        spmm_csr_kernel<<<(NP * 32 + B - 1) / B, B>>>(ppu_ptr, ppu_cv, pmsg, pprop, NP);
        update_kernel<<<(NTOT / 8 + B - 1) / B, B>>>(lk0[l], lk1[l], l == 2,
                                                     (const float4*)xcur,
                                                     (const float4*)acur,
                                                     (float4*)out);
    }
}

// round 5
// speedup vs baseline: 1.8801x; 1.7509x over previous
#include <cuda_runtime.h>
#include <cstdint>

#define NP   200000
#define NU   50000
#define NNZE 2000000
#define DIM  64
#define NTOT (NP*DIM)      /* 12,800,000 */
#define MSGN (NU*DIM)      /*  3,200,000 */

__device__ __align__(16) float g_x[NTOT];
__device__ __align__(16) float g_acc[NTOT];
__device__ __align__(16) float g_msg[MSGN];

// CSR scratch
__device__ int  g_up_ptr[NU + 1];
__device__ int  g_up_off[NU];
__device__ int2 g_up_cv[NNZE];     // packed (col, val-bits), row-grouped
__device__ int  g_pu_ptr[NP + 1];
__device__ int  g_pu_off[NP];
__device__ int2 g_pu_cv[NNZE];
__device__ int  g_bsum[256];

// ---------------- threefry2x32 (exact JAX semantics) ----------------
__host__ __device__ __forceinline__ uint32_t rotl32(uint32_t x, int d) {
    return (x << d) | (x >> (32 - d));
}

__host__ __device__ __forceinline__ void tf2x32(uint32_t k0, uint32_t k1,
                                                uint32_t x0, uint32_t x1,
                                                uint32_t &o0, uint32_t &o1) {
    uint32_t ks2 = k0 ^ k1 ^ 0x1BD11BDAu;
    x0 += k0; x1 += k1;
#define TFR(r) { x0 += x1; x1 = rotl32(x1, (r)); x1 ^= x0; }
    TFR(13) TFR(15) TFR(26) TFR(6)
    x0 += k1;  x1 += ks2 + 1u;
    TFR(17) TFR(29) TFR(16) TFR(24)
    x0 += ks2; x1 += k0 + 2u;
    TFR(13) TFR(15) TFR(26) TFR(6)
    x0 += k0;  x1 += k1 + 3u;
    TFR(17) TFR(29) TFR(16) TFR(24)
    x0 += k1;  x1 += ks2 + 4u;
    TFR(13) TFR(15) TFR(26) TFR(6)
    x0 += ks2; x1 += k0 + 5u;
#undef TFR
    o0 = x0; o1 = x1;
}

// partitionable threefry draw for element e (counter (0, e)), 32-bit: out0 ^ out1
__device__ __forceinline__ uint32_t tf_bits(uint32_t k0, uint32_t k1, uint32_t e) {
    uint32_t o0, o1;
    tf2x32(k0, k1, 0u, e, o0, o1);
    return o0 ^ o1;
}

__device__ __forceinline__ float dropv(uint32_t bits, float s) {
    return (bits & 0x80000000u) ? 0.f : 2.f * s;   // keep iff MSB==0, scale 1/keep=2
}

// ---------------- CSR build ----------------
__global__ void zero_cnt_kernel() {
    int i = blockIdx.x * blockDim.x + threadIdx.x;
    if (i <= NU) g_up_ptr[i] = 0;
    if (i <= NP) g_pu_ptr[i] = 0;
}

__global__ void hist_kernel(const int* __restrict__ up_rows,
                            const int* __restrict__ pu_rows) {
    int e = blockIdx.x * blockDim.x + threadIdx.x;
    if (e >= NNZE) return;
    atomicAdd(&g_up_ptr[__ldg(up_rows + e)], 1);
    atomicAdd(&g_pu_ptr[__ldg(pu_rows + e)], 1);
}

// pass 1: per-block (1024) exclusive scan; excl -> off, block total -> g_bsum
__global__ void scan1_kernel(const int* __restrict__ cnt, int* __restrict__ excl,
                             int n) {
    __shared__ int ws[32];
    int t = threadIdx.x;
    int i = blockIdx.x * 1024 + t;
    int v = (i < n) ? cnt[i] : 0;
    int x = v;
#pragma unroll
    for (int d = 1; d < 32; d <<= 1) {
        int u = __shfl_up_sync(~0u, x, d);
        if ((t & 31) >= d) x += u;
    }
    if ((t & 31) == 31) ws[t >> 5] = x;
    __syncthreads();
    if (t < 32) {
        int w = ws[t];
#pragma unroll
        for (int d = 1; d < 32; d <<= 1) {
            int u = __shfl_up_sync(~0u, w, d);
            if (t >= d) w += u;
        }
        ws[t] = w;
    }
    __syncthreads();
    int base = (t >= 32) ? ws[(t >> 5) - 1] : 0;
    int incl = x + base;
    if (i < n) excl[i] = incl - v;
    if (t == 1023) g_bsum[blockIdx.x] = incl;
}

// pass 2: exclusive scan of <=256 block sums in place; total -> ptr[n]
__global__ void scan2_kernel(int nb, int* __restrict__ ptr_n) {
    __shared__ int ws[8];
    int t = threadIdx.x;       // 256 threads
    int v = (t < nb) ? g_bsum[t] : 0;
    int x = v;
#pragma unroll
    for (int d = 1; d < 32; d <<= 1) {
        int u = __shfl_up_sync(~0u, x, d);
        if ((t & 31) >= d) x += u;
    }
    if ((t & 31) == 31) ws[t >> 5] = x;
    __syncthreads();
    if (t < 8) {
        int w = ws[t];
#pragma unroll
        for (int d = 1; d < 8; d <<= 1) {
            int u = __shfl_up_sync(0xffu, w, d);
            if (t >= d) w += u;
        }
        ws[t] = w;
    }
    __syncthreads();
    int base = (t >= 32) ? ws[(t >> 5) - 1] : 0;
    int incl = x + base;
    if (t < nb) g_bsum[t] = incl - v;
    if (t == nb - 1) *ptr_n = incl;
}

// pass 3: add block offset; write both ptr and off
__global__ void scan3_kernel(int* __restrict__ ptr, int* __restrict__ off, int n) {
    int i = blockIdx.x * 1024 + threadIdx.x;
    if (i < n) {
        int v = off[i] + g_bsum[blockIdx.x];
        ptr[i] = v;
        off[i] = v;
    }
}

__global__ void scatter_kernel(const int* __restrict__ up_rows,
                               const int* __restrict__ up_cols,
                               const float* __restrict__ up_vals,
                               const int* __restrict__ pu_rows,
                               const int* __restrict__ pu_cols,
                               const float* __restrict__ pu_vals) {
    int e = blockIdx.x * blockDim.x + threadIdx.x;
    if (e >= NNZE) return;
    {
        int r = __ldg(up_rows + e);
        int p = atomicAdd(&g_up_off[r], 1);
        g_up_cv[p] = make_int2(__ldg(up_cols + e), __float_as_int(__ldg(up_vals + e)));
    }
    {
        int r = __ldg(pu_rows + e);
        int p = atomicAdd(&g_pu_off[r], 1);
        g_pu_cv[p] = make_int2(__ldg(pu_cols + e), __float_as_int(__ldg(pu_vals + e)));
    }
}

// ---------------- UP SpMM: one warp per U-row, float2 per lane ----------------
__global__ void spmm_up_kernel(const float* __restrict__ xin) {
    int w = (blockIdx.x * blockDim.x + threadIdx.x) >> 5;
    if (w >= NU) return;
    int lane = threadIdx.x & 31;
    int s = __ldg(g_up_ptr + w), e = __ldg(g_up_ptr + w + 1);
    float2 acc = make_float2(0.f, 0.f);
    for (int j = s; j < e; ++j) {
        int2 cv = __ldg(g_up_cv + j);
        float v = __int_as_float(cv.y);
        float2 xv = *reinterpret_cast<const float2*>(xin + (size_t)cv.x * DIM + lane * 2);
        acc.x += v * xv.x;
        acc.y += v * xv.y;
    }
    *reinterpret_cast<float2*>(g_msg + (size_t)w * DIM + lane * 2) = acc;
}

// ---------------- PU SpMM fused with residual + dropout + acc ----------------
__global__ void spmm_pu_fused_kernel(const float* __restrict__ x_in,
                                     const float* __restrict__ acc_in,
                                     uint32_t k0, uint32_t k1, int last,
                                     float* __restrict__ out) {
    int w = (blockIdx.x * blockDim.x + threadIdx.x) >> 5;
    if (w >= NP) return;
    int lane = threadIdx.x & 31;
    int s = __ldg(g_pu_ptr + w), e = __ldg(g_pu_ptr + w + 1);
    float2 acc = make_float2(0.f, 0.f);
    for (int j = s; j < e; ++j) {
        int2 cv = __ldg(g_pu_cv + j);
        float v = __int_as_float(cv.y);
        float2 xv = *reinterpret_cast<const float2*>(g_msg + (size_t)cv.x * DIM + lane * 2);
        acc.x += v * xv.x;
        acc.y += v * xv.y;
    }
    size_t idx = (size_t)w * DIM + lane * 2;
    uint32_t e0 = (uint32_t)idx;
    uint32_t b0 = tf_bits(k0, k1, e0);
    uint32_t b1 = tf_bits(k0, k1, e0 + 1u);

    float2 xv = *reinterpret_cast<const float2*>(x_in + idx);
    float2 av = *reinterpret_cast<const float2*>(acc_in + idx);
    float n0 = dropv(b0, acc.x + xv.x);
    float n1 = dropv(b1, acc.y + xv.y);
    float a0 = av.x + n0;
    float a1 = av.y + n1;

    if (last) {
        *reinterpret_cast<float2*>(out + idx) = make_float2(a0 * 0.25f, a1 * 0.25f);
    } else {
        *reinterpret_cast<float2*>(g_x + idx)   = make_float2(n0, n1);
        *reinterpret_cast<float2*>(g_acc + idx) = make_float2(a0, a1);
    }
}

// ---------------- launch ----------------
// Inputs in dict/insertion order:
//   d_in[0]=pois_embs, d_in[1]=up_rows, d_in[2]=up_cols, d_in[3]=up_vals,
//   d_in[4]=pu_rows,   d_in[5]=pu_cols, d_in[6]=pu_vals
extern "C" void kernel_launch(void* const* d_in, const int* in_sizes, int n_in,
                              void* d_out, int out_size) {
    const float* pois    = (const float*)d_in[0];
    const int*   up_rows = (const int*)  d_in[1];
    const int*   up_cols = (const int*)  d_in[2];
    const float* up_vals = (const float*)d_in[3];
    const int*   pu_rows = (const int*)  d_in[4];
    const int*   pu_cols = (const int*)  d_in[5];
    const float* pu_vals = (const float*)d_in[6];
    float* out = (float*)d_out;

    float *px, *pacc;
    int *pup_ptr, *pup_off, *ppu_ptr, *ppu_off;
    cudaGetSymbolAddress((void**)&px,      g_x);
    cudaGetSymbolAddress((void**)&pacc,    g_acc);
    cudaGetSymbolAddress((void**)&pup_ptr, g_up_ptr);
    cudaGetSymbolAddress((void**)&pup_off, g_up_off);
    cudaGetSymbolAddress((void**)&ppu_ptr, g_pu_ptr);
    cudaGetSymbolAddress((void**)&ppu_off, g_pu_off);

    // per-layer dropout keys: fold_in(key(42), l) = threefry((0,42),(0,l))
    uint32_t lk0[3], lk1[3];
    for (int l = 0; l < 3; ++l)
        tf2x32(0u, 42u, 0u, (uint32_t)l, lk0[l], lk1[l]);

    const int B = 256;
    const int NB_U = (NU + 1023) / 1024;   // 49
    const int NB_P = (NP + 1023) / 1024;   // 196

    // ---- CSR build (once per call, reused by all 3 layers) ----
    zero_cnt_kernel<<<(NP + 1 + B - 1) / B, B>>>();
    hist_kernel<<<(NNZE + B - 1) / B, B>>>(up_rows, pu_rows);
    // UP scan
    scan1_kernel<<<NB_U, 1024>>>(pup_ptr, pup_off, NU);
    scan2_kernel<<<1, 256>>>(NB_U, pup_ptr + NU);
    scan3_kernel<<<NB_U, 1024>>>(pup_ptr, pup_off, NU);
    // PU scan
    scan1_kernel<<<NB_P, 1024>>>(ppu_ptr, ppu_off, NP);
    scan2_kernel<<<1, 256>>>(NB_P, ppu_ptr + NP);
    scan3_kernel<<<NB_P, 1024>>>(ppu_ptr, ppu_off, NP);

    scatter_kernel<<<(NNZE + B - 1) / B, B>>>(up_rows, up_cols, up_vals,
                                              pu_rows, pu_cols, pu_vals);

    // ---- 3 layers ----
    for (int l = 0; l < 3; ++l) {
        const float* xcur = (l == 0) ? pois : px;
        const float* acur = (l == 0) ? pois : pacc;
        spmm_up_kernel<<<(NU * 32 + B - 1) / B, B>>>(xcur);
        spmm_pu_fused_kernel<<<(NP * 32 + B - 1) / B, B>>>(xcur, acur,
                                                           lk0[l], lk1[l],
                                                           l == 2, out);
    }
}

// round 6
// speedup vs baseline: 1.9312x; 1.0272x over previous
#include <cuda_runtime.h>
#include <cuda_bf16.h>
#include <cstdint>

#define NP   200000
#define NU   50000
#define NNZE 2000000
#define DIM  64
#define NTOT (NP*DIM)      /* 12,800,000 */
#define MSGN (NU*DIM)      /*  3,200,000 */

__device__ __align__(16) float g_x[NTOT];
__device__ __align__(16) float g_acc[NTOT];
__device__ __align__(16) __nv_bfloat162 g_xh[NTOT / 2];    // bf16 mirror of x (gather operand)
__device__ __align__(16) __nv_bfloat162 g_msgh[MSGN / 2];  // bf16 msg (gather operand)

// CSR scratch
__device__ int  g_up_ptr[NU + 1];
__device__ int  g_up_off[NU];
__device__ int2 g_up_cv[NNZE];     // packed (col, val-bits), row-grouped
__device__ int  g_pu_ptr[NP + 1];
__device__ int  g_pu_off[NP];
__device__ int2 g_pu_cv[NNZE];
__device__ int  g_bsum[256];

// ---------------- threefry2x32 (exact JAX semantics) ----------------
__host__ __device__ __forceinline__ uint32_t rotl32(uint32_t x, int d) {
    return (x << d) | (x >> (32 - d));
}

__host__ __device__ __forceinline__ void tf2x32(uint32_t k0, uint32_t k1,
                                                uint32_t x0, uint32_t x1,
                                                uint32_t &o0, uint32_t &o1) {
    uint32_t ks2 = k0 ^ k1 ^ 0x1BD11BDAu;
    x0 += k0; x1 += k1;
#define TFR(r) { x0 += x1; x1 = rotl32(x1, (r)); x1 ^= x0; }
    TFR(13) TFR(15) TFR(26) TFR(6)
    x0 += k1;  x1 += ks2 + 1u;
    TFR(17) TFR(29) TFR(16) TFR(24)
    x0 += ks2; x1 += k0 + 2u;
    TFR(13) TFR(15) TFR(26) TFR(6)
    x0 += k0;  x1 += k1 + 3u;
    TFR(17) TFR(29) TFR(16) TFR(24)
    x0 += k1;  x1 += ks2 + 4u;
    TFR(13) TFR(15) TFR(26) TFR(6)
    x0 += ks2; x1 += k0 + 5u;
#undef TFR
    o0 = x0; o1 = x1;
}

// partitionable threefry draw for element e (counter (0, e)), 32-bit: out0 ^ out1
__device__ __forceinline__ uint32_t tf_bits(uint32_t k0, uint32_t k1, uint32_t e) {
    uint32_t o0, o1;
    tf2x32(k0, k1, 0u, e, o0, o1);
    return o0 ^ o1;
}

__device__ __forceinline__ float dropv(uint32_t bits, float s) {
    return (bits & 0x80000000u) ? 0.f : 2.f * s;   // keep iff MSB==0, scale 1/keep=2
}

// ---------------- CSR build ----------------
__global__ void zero_cnt_kernel() {
    int i = blockIdx.x * blockDim.x + threadIdx.x;
    if (i <= NU) g_up_ptr[i] = 0;
    if (i <= NP) g_pu_ptr[i] = 0;
}

__global__ void hist_kernel(const int* __restrict__ up_rows,
                            const int* __restrict__ pu_rows) {
    int e = blockIdx.x * blockDim.x + threadIdx.x;
    if (e >= NNZE) return;
    atomicAdd(&g_up_ptr[__ldg(up_rows + e)], 1);
    atomicAdd(&g_pu_ptr[__ldg(pu_rows + e)], 1);
}

// pass 1: per-block (1024) exclusive scan; excl -> off, block total -> g_bsum
__global__ void scan1_kernel(const int* __restrict__ cnt, int* __restrict__ excl,
                             int n) {
    __shared__ int ws[32];
    int t = threadIdx.x;
    int i = blockIdx.x * 1024 + t;
    int v = (i < n) ? cnt[i] : 0;
    int x = v;
#pragma unroll
    for (int d = 1; d < 32; d <<= 1) {
        int u = __shfl_up_sync(~0u, x, d);
        if ((t & 31) >= d) x += u;
    }
    if ((t & 31) == 31) ws[t >> 5] = x;
    __syncthreads();
    if (t < 32) {
        int w = ws[t];
#pragma unroll
        for (int d = 1; d < 32; d <<= 1) {
            int u = __shfl_up_sync(~0u, w, d);
            if (t >= d) w += u;
        }
        ws[t] = w;
    }
    __syncthreads();
    int base = (t >= 32) ? ws[(t >> 5) - 1] : 0;
    int incl = x + base;
    if (i < n) excl[i] = incl - v;
    if (t == 1023) g_bsum[blockIdx.x] = incl;
}

// pass 2: exclusive scan of <=256 block sums in place; total -> ptr[n]
__global__ void scan2_kernel(int nb, int* __restrict__ ptr_n) {
    __shared__ int ws[8];
    int t = threadIdx.x;       // 256 threads
    int v = (t < nb) ? g_bsum[t] : 0;
    int x = v;
#pragma unroll
    for (int d = 1; d < 32; d <<= 1) {
        int u = __shfl_up_sync(~0u, x, d);
        if ((t & 31) >= d) x += u;
    }
    if ((t & 31) == 31) ws[t >> 5] = x;
    __syncthreads();
    if (t < 8) {
        int w = ws[t];
#pragma unroll
        for (int d = 1; d < 8; d <<= 1) {
            int u = __shfl_up_sync(0xffu, w, d);
            if (t >= d) w += u;
        }
        ws[t] = w;
    }
    __syncthreads();
    int base = (t >= 32) ? ws[(t >> 5) - 1] : 0;
    int incl = x + base;
    if (t < nb) g_bsum[t] = incl - v;
    if (t == nb - 1) *ptr_n = incl;
}

// pass 3: add block offset; write both ptr and off
__global__ void scan3_kernel(int* __restrict__ ptr, int* __restrict__ off, int n) {
    int i = blockIdx.x * 1024 + threadIdx.x;
    if (i < n) {
        int v = off[i] + g_bsum[blockIdx.x];
        ptr[i] = v;
        off[i] = v;
    }
}

__global__ void scatter_kernel(const int* __restrict__ up_rows,
                               const int* __restrict__ up_cols,
                               const float* __restrict__ up_vals,
                               const int* __restrict__ pu_rows,
                               const int* __restrict__ pu_cols,
                               const float* __restrict__ pu_vals) {
    int e = blockIdx.x * blockDim.x + threadIdx.x;
    if (e >= NNZE) return;
    {
        int r = __ldg(up_rows + e);
        int p = atomicAdd(&g_up_off[r], 1);
        g_up_cv[p] = make_int2(__ldg(up_cols + e), __float_as_int(__ldg(up_vals + e)));
    }
    {
        int r = __ldg(pu_rows + e);
        int p = atomicAdd(&g_pu_off[r], 1);
        g_pu_cv[p] = make_int2(__ldg(pu_cols + e), __float_as_int(__ldg(pu_vals + e)));
    }
}

// ---------------- fp32 -> bf16 mirror (layer 0 only) ----------------
__global__ void cvt_kernel(const float4* __restrict__ src) {
    int i = blockIdx.x * blockDim.x + threadIdx.x;   // one float4 -> two bf162
    if (i >= NTOT / 4) return;
    float4 v = src[i];
    g_xh[2 * i]     = __floats2bfloat162_rn(v.x, v.y);
    g_xh[2 * i + 1] = __floats2bfloat162_rn(v.z, v.w);
}

// ---------------- UP SpMM: one warp per U-row; bf16 gather, fp32 accum ----
__global__ void spmm_up_kernel() {
    int w = (blockIdx.x * blockDim.x + threadIdx.x) >> 5;
    if (w >= NU) return;
    int lane = threadIdx.x & 31;
    int s = __ldg(g_up_ptr + w), e = __ldg(g_up_ptr + w + 1);
    float accx = 0.f, accy = 0.f;
    for (int j = s; j < e; ++j) {
        int2 cv = __ldg(g_up_cv + j);                // same addr all lanes: broadcast
        float v = __int_as_float(cv.y);
        float2 xv = __bfloat1622float2(g_xh[(size_t)cv.x * (DIM / 2) + lane]);
        accx += v * xv.x;
        accy += v * xv.y;
    }
    g_msgh[(size_t)w * (DIM / 2) + lane] = __floats2bfloat162_rn(accx, accy);
}

// ---------------- PU SpMM fused with residual + dropout + acc ----------------
__global__ void spmm_pu_fused_kernel(const float* __restrict__ x_in,
                                     const float* __restrict__ acc_in,
                                     uint32_t k0, uint32_t k1, int last,
                                     float* __restrict__ out) {
    int w = (blockIdx.x * blockDim.x + threadIdx.x) >> 5;
    if (w >= NP) return;
    int lane = threadIdx.x & 31;
    int s = __ldg(g_pu_ptr + w), e = __ldg(g_pu_ptr + w + 1);
    float accx = 0.f, accy = 0.f;
    for (int j = s; j < e; ++j) {
        int2 cv = __ldg(g_pu_cv + j);
        float v = __int_as_float(cv.y);
        float2 xv = __bfloat1622float2(g_msgh[(size_t)cv.x * (DIM / 2) + lane]);
        accx += v * xv.x;
        accy += v * xv.y;
    }
    size_t idx = (size_t)w * DIM + lane * 2;
    uint32_t e0 = (uint32_t)idx;
    uint32_t b0 = tf_bits(k0, k1, e0);
    uint32_t b1 = tf_bits(k0, k1, e0 + 1u);

    float2 xv = *reinterpret_cast<const float2*>(x_in + idx);
    float2 av = *reinterpret_cast<const float2*>(acc_in + idx);
    float n0 = dropv(b0, accx + xv.x);
    float n1 = dropv(b1, accy + xv.y);
    float a0 = av.x + n0;
    float a1 = av.y + n1;

    if (last) {
        *reinterpret_cast<float2*>(out + idx) = make_float2(a0 * 0.25f, a1 * 0.25f);
    } else {
        *reinterpret_cast<float2*>(g_x + idx)   = make_float2(n0, n1);
        *reinterpret_cast<float2*>(g_acc + idx) = make_float2(a0, a1);
        g_xh[idx / 2] = __floats2bfloat162_rn(n0, n1);
    }
}

// ---------------- launch ----------------
// Inputs in dict/insertion order:
//   d_in[0]=pois_embs, d_in[1]=up_rows, d_in[2]=up_cols, d_in[3]=up_vals,
//   d_in[4]=pu_rows,   d_in[5]=pu_cols, d_in[6]=pu_vals
extern "C" void kernel_launch(void* const* d_in, const int* in_sizes, int n_in,
                              void* d_out, int out_size) {
    const float* pois    = (const float*)d_in[0];
    const int*   up_rows = (const int*)  d_in[1];
    const int*   up_cols = (const int*)  d_in[2];
    const float* up_vals = (const float*)d_in[3];
    const int*   pu_rows = (const int*)  d_in[4];
    const int*   pu_cols = (const int*)  d_in[5];
    const float* pu_vals = (const float*)d_in[6];
    float* out = (float*)d_out;

    float *px, *pacc;
    int *pup_ptr, *pup_off, *ppu_ptr, *ppu_off;
    cudaGetSymbolAddress((void**)&px,      g_x);
    cudaGetSymbolAddress((void**)&pacc,    g_acc);
    cudaGetSymbolAddress((void**)&pup_ptr, g_up_ptr);
    cudaGetSymbolAddress((void**)&pup_off, g_up_off);
    cudaGetSymbolAddress((void**)&ppu_ptr, g_pu_ptr);
    cudaGetSymbolAddress((void**)&ppu_off, g_pu_off);

    // per-layer dropout keys: fold_in(key(42), l) = threefry((0,42),(0,l))
    uint32_t lk0[3], lk1[3];
    for (int l = 0; l < 3; ++l)
        tf2x32(0u, 42u, 0u, (uint32_t)l, lk0[l], lk1[l]);

    const int B = 256;
    const int NB_U = (NU + 1023) / 1024;   // 49
    const int NB_P = (NP + 1023) / 1024;   // 196

    // ---- CSR build (once per call, reused by all 3 layers) ----
    zero_cnt_kernel<<<(NP + 1 + B - 1) / B, B>>>();
    hist_kernel<<<(NNZE + B - 1) / B, B>>>(up_rows, pu_rows);
    scan1_kernel<<<NB_U, 1024>>>(pup_ptr, pup_off, NU);
    scan2_kernel<<<1, 256>>>(NB_U, pup_ptr + NU);
    scan3_kernel<<<NB_U, 1024>>>(pup_ptr, pup_off, NU);
    scan1_kernel<<<NB_P, 1024>>>(ppu_ptr, ppu_off, NP);
    scan2_kernel<<<1, 256>>>(NB_P, ppu_ptr + NP);
    scan3_kernel<<<NB_P, 1024>>>(ppu_ptr, ppu_off, NP);
    scatter_kernel<<<(NNZE + B - 1) / B, B>>>(up_rows, up_cols, up_vals,
                                              pu_rows, pu_cols, pu_vals);

    // bf16 mirror of layer-0 x (= pois)
    cvt_kernel<<<(NTOT / 4 + B - 1) / B, B>>>((const float4*)pois);

    // ---- 3 layers ----
    for (int l = 0; l < 3; ++l) {
        const float* xcur = (l == 0) ? pois : px;
        const float* acur = (l == 0) ? pois : pacc;
        spmm_up_kernel<<<(NU * 32 + B - 1) / B, B>>>();
        spmm_pu_fused_kernel<<<(NP * 32 + B - 1) / B, B>>>(xcur, acur,
                                                           lk0[l], lk1[l],
                                                           l == 2, out);
    }
}